// round 14
// baseline (speedup 1.0000x reference)
#include <cuda_runtime.h>

constexpr int VOCAB = 50257;
constexpr int DIM   = 50;
constexpr int NU2   = 64;
constexpr int NB    = 1024;
constexpr int NT    = 1024;

using u64 = unsigned long long;

// Precomputed embedding projection: embproj[v][k] = emb[v]@kx1[:,k] + b1[0][k]
// 50257*96 floats = 19.3 MB -> L2 resident during the recurrent kernel.
__device__ float g_embproj[(size_t)VOCAB * 96];

__device__ __forceinline__ u64 pack2(float lo, float hi) {
    u64 r; asm("mov.b64 %0, {%1, %2};" : "=l"(r) : "f"(lo), "f"(hi)); return r;
}
__device__ __forceinline__ void unpack2(u64 p, float& lo, float& hi) {
    asm("mov.b64 {%0, %1}, %2;" : "=f"(lo), "=f"(hi) : "l"(p));
}
__device__ __forceinline__ u64 fma2(u64 a, u64 b, u64 c) {
    u64 d; asm("fma.rn.f32x2 %0, %1, %2, %3;" : "=l"(d) : "l"(a), "l"(b), "l"(c)); return d;
}
__device__ __forceinline__ u64 add2(u64 a, u64 b) {
    u64 d; asm("add.rn.f32x2 %0, %1, %2;" : "=l"(d) : "l"(a), "l"(b)); return d;
}
__device__ __forceinline__ float hsum2(u64 p) {
    float lo, hi; unpack2(p, lo, hi); return lo + hi;
}
// Fast activations via single-MUFU tanh (sm_75+). abs err ~1e-5, fine vs 1e-3.
__device__ __forceinline__ float tanh_mufu(float x) {
    float t; asm("tanh.approx.f32 %0, %1;" : "=f"(t) : "f"(x)); return t;
}
__device__ __forceinline__ float sigf(float x) {
    return fmaf(tanh_mufu(0.5f * x), 0.5f, 0.5f);
}

// ---------------------------------------------------------------------------
// Kernel A: embproj = emb @ kx1 + b1[0]
// ---------------------------------------------------------------------------
__global__ void __launch_bounds__(96) embproj_kernel(const float* __restrict__ emb,
                                                     const float* __restrict__ kx1,
                                                     const float* __restrict__ b1) {
    __shared__ float kx1s[DIM * 96];
    __shared__ float xrow[DIM];
    const int tid = threadIdx.x;
    for (int i = tid; i < DIM * 96; i += 96) kx1s[i] = kx1[i];
    const float bc = b1[tid];
    __syncthreads();
    const int row0 = blockIdx.x * 16;
    for (int k = 0; k < 16; k++) {
        const int row = row0 + k;
        if (row >= VOCAB) break;
        if (tid < DIM) xrow[tid] = emb[(size_t)row * DIM + tid];
        __syncthreads();
        float acc = bc;
        #pragma unroll
        for (int d = 0; d < DIM; d++) acc = fmaf(xrow[d], kx1s[d * 96 + tid], acc);
        g_embproj[(size_t)row * 96 + tid] = acc;
        __syncthreads();
    }
}

// ---------------------------------------------------------------------------
// Kernel B: fused GRU1 -> GRU2 -> GLU -> dense.
// 296 blocks x 256 threads (8 warps), 2 CTAs/SM -> 16 warps/SM = 4/SMSP.
// Blocks [0,136): 4 elems; [136,296): 3 elems; warp w owns elem w (w < NE).
// Weights register-resident, j-split EIGHT ways across warps (halves weight
// regs vs R13 so 2x the warps fit the RF at 128 regs/thread):
//   kh2 rows [8w,8w+8), kx2 rows [4w,4w+4), kh1 rows [4w,4w+4).
// Biases live in smem (reg relief). Same 3-phase step as R10/R13:
//   A: GRU1 combine -> h1(t); rec2 partials -> pX 3..5;   BAR1
//   B: xproj2 + rec1(t+1) partials -> pX 0..2, pR;        BAR2
//   C: combine -> GRU2 gates -> h2(t); publish;           BAR3
//
// smem (float units), per CTA 64,384 B (2 CTAs = 125.8 KB/SM):
//   [0,12288)      pX    u64[4 elems][8 warps][6 slots][32]
//   [12288,14336)  pRzr  u64[4][8][32]
//   [14336,15360)  pRh   f32[4][8][32]
//   [15360,15488)  h1s   f32[4][32]
//   [15488,15744)  h2s   f32[4][64]
//   [15744,16096)  biases (azr1b u64[32], bg1 f32[32], bz2/br2/bxh2/bhh2 u64[32])
// ---------------------------------------------------------------------------
constexpr int SMEM_FLOATS = 16096;

template<int NE>
__device__ __forceinline__ void rnn_scan(
    const int* __restrict__ tok, bool owns, int wid, int l,
    u64* pX, u64* pRzr, float* pRh, float* h1s, float* h2s,
    const u64* bAzr1, const float* bG1, const u64* bZ2, const u64* bR2,
    const u64* bXH2, const u64* bHH2,
    const u64* wzA, const u64* wzB, const u64* wrA, const u64* wrB,
    const u64* whA, const u64* whB,
    const u64* xzA, const u64* xzB, const u64* xrA, const u64* xrB,
    const u64* xhA, const u64* xhB,
    const u64* k1z, const u64* k1r, const u64* k1h,
    float& h1o, float& h2a, float& h2b)
{
    // --- prologue: embproj gather for t=0 ---
    int tk = 0;
    float xz = 0.0f, xr = 0.0f, xh = 0.0f;
    if (owns) {
        tk = tok[l];
        const int ti = __shfl_sync(0xffffffffu, tk, 0);
        const float* ep = g_embproj + (size_t)ti * 96;
        xz = __ldg(ep + l); xr = __ldg(ep + 32 + l); xh = __ldg(ep + 64 + l);
    }

    for (int t = 0; t < NT; t++) {
        // ===== Phase A =====================================================
        // GRU1 combine first (its LDS+MUFU chain hides under rec2 fma2s).
        if (owns) {
            u64 zr = bAzr1[l]; float hm = bG1[l];
            #pragma unroll
            for (int w = 0; w < 8; w++) {
                zr = add2(zr, pRzr[(wid * 8 + w) * 32 + l]);
                hm += pRh[(wid * 8 + w) * 32 + l];
            }
            float az, ar; unpack2(zr, az, ar);
            const float z = sigf(xz + az), r = sigf(xr + ar);
            const float hh = tanh_mufu(xh + r * hm);
            h1o = z * h1o + (1.0f - z) * hh;
            h1s[wid * 32 + l] = h1o;
        }

        // rec2 partials from h2(t-1), kh2 rows [8w,8w+8), even/odd packed
        #pragma unroll
        for (int e = 0; e < NE; e++) {
            const ulonglong2* hp = (const ulonglong2*)(h2s + e * 64 + wid * 8);
            const ulonglong2 q0 = hp[0], q1 = hp[1];   // {h_2p, h_2p+1} pairs
            u64 azAa = 0ull, azBa = 0ull, arAa = 0ull, arBa = 0ull,
                ahAa = 0ull, ahBa = 0ull;
            azAa = fma2(wzA[0], q0.x, azAa); azBa = fma2(wzB[0], q0.x, azBa);
            arAa = fma2(wrA[0], q0.x, arAa); arBa = fma2(wrB[0], q0.x, arBa);
            ahAa = fma2(whA[0], q0.x, ahAa); ahBa = fma2(whB[0], q0.x, ahBa);
            azAa = fma2(wzA[1], q0.y, azAa); azBa = fma2(wzB[1], q0.y, azBa);
            arAa = fma2(wrA[1], q0.y, arAa); arBa = fma2(wrB[1], q0.y, arBa);
            ahAa = fma2(whA[1], q0.y, ahAa); ahBa = fma2(whB[1], q0.y, ahBa);
            azAa = fma2(wzA[2], q1.x, azAa); azBa = fma2(wzB[2], q1.x, azBa);
            arAa = fma2(wrA[2], q1.x, arAa); arBa = fma2(wrB[2], q1.x, arBa);
            ahAa = fma2(whA[2], q1.x, ahAa); ahBa = fma2(whB[2], q1.x, ahBa);
            azAa = fma2(wzA[3], q1.y, azAa); azBa = fma2(wzB[3], q1.y, azBa);
            arAa = fma2(wrA[3], q1.y, arAa); arBa = fma2(wrB[3], q1.y, arBa);
            ahAa = fma2(whA[3], q1.y, ahAa); ahBa = fma2(whB[3], q1.y, ahBa);
            u64* pb = pX + (size_t)((e * 8 + wid) * 6) * 32 + l;
            pb[96]  = pack2(hsum2(azAa), hsum2(azBa));   // rec z (cols l, l+32)
            pb[128] = pack2(hsum2(arAa), hsum2(arBa));   // rec r
            pb[160] = pack2(hsum2(ahAa), hsum2(ahBa));   // rec h
        }

        // prefetch embproj for t+1 (lands long before next Phase A)
        if (owns && t + 1 < NT) {
            if (((t + 1) & 31) == 0) tk = tok[t + 1 + l];
            const int ti = __shfl_sync(0xffffffffu, tk, (t + 1) & 31);
            const float* ep = g_embproj + (size_t)ti * 96;
            xz = __ldg(ep + l); xr = __ldg(ep + 32 + l); xh = __ldg(ep + 64 + l);
        }
        __syncthreads();              // BAR1: h1(t), rec2 partials published

        // ===== Phase B: xproj2 + rec1(t+1) partials from h1(t) =============
        #pragma unroll
        for (int e = 0; e < NE; e++) {
            const ulonglong2* hq = (const ulonglong2*)(h1s + e * 32 + wid * 4);
            const ulonglong2 q = hq[0];                // 2 pairs {h_2p, h_2p+1}
            u64 sxzA = 0ull, sxzB = 0ull, sxrA = 0ull, sxrB = 0ull,
                sxhA = 0ull, sxhB = 0ull, srz = 0ull, srr = 0ull, srh = 0ull;
            sxzA = fma2(xzA[0], q.x, sxzA); sxzB = fma2(xzB[0], q.x, sxzB);
            sxrA = fma2(xrA[0], q.x, sxrA); sxrB = fma2(xrB[0], q.x, sxrB);
            sxhA = fma2(xhA[0], q.x, sxhA); sxhB = fma2(xhB[0], q.x, sxhB);
            srz  = fma2(k1z[0], q.x, srz);  srr  = fma2(k1r[0], q.x, srr);
            srh  = fma2(k1h[0], q.x, srh);
            sxzA = fma2(xzA[1], q.y, sxzA); sxzB = fma2(xzB[1], q.y, sxzB);
            sxrA = fma2(xrA[1], q.y, sxrA); sxrB = fma2(xrB[1], q.y, sxrB);
            sxhA = fma2(xhA[1], q.y, sxhA); sxhB = fma2(xhB[1], q.y, sxhB);
            srz  = fma2(k1z[1], q.y, srz);  srr  = fma2(k1r[1], q.y, srr);
            srh  = fma2(k1h[1], q.y, srh);
            u64* pb = pX + (size_t)((e * 8 + wid) * 6) * 32 + l;
            pb[0]  = pack2(hsum2(sxzA), hsum2(sxzB));   // x z
            pb[32] = pack2(hsum2(sxrA), hsum2(sxrB));   // x r
            pb[64] = pack2(hsum2(sxhA), hsum2(sxhB));   // x h
            pRzr[(e * 8 + wid) * 32 + l] = pack2(hsum2(srz), hsum2(srr));
            pRh [(e * 8 + wid) * 32 + l] = hsum2(srh);
        }
        __syncthreads();              // BAR2: partials published

        // ===== Phase C: combine -> GRU2 gates -> h2(t) =====================
        if (owns) {
            u64 zp = bZ2[l], rp = bR2[l], xp = bXH2[l], hm = bHH2[l];
            #pragma unroll
            for (int w = 0; w < 8; w++) {
                const u64* pb = pX + (size_t)((wid * 8 + w) * 6) * 32 + l;
                zp = add2(zp, pb[0]);
                rp = add2(rp, pb[32]);
                xp = add2(xp, pb[64]);
                zp = add2(zp, pb[96]);
                rp = add2(rp, pb[128]);
                hm = add2(hm, pb[160]);
            }
            float zl, zh_, rl, rh_, xpl, xph, ml, mh;
            unpack2(zp, zl, zh_); unpack2(rp, rl, rh_);
            unpack2(xp, xpl, xph); unpack2(hm, ml, mh);
            {
                const float z = sigf(zl), r = sigf(rl);
                const float hh = tanh_mufu(xpl + r * ml);
                h2a = z * h2a + (1.0f - z) * hh;
            }
            {
                const float z = sigf(zh_), r = sigf(rh_);
                const float hh = tanh_mufu(xph + r * mh);
                h2b = z * h2b + (1.0f - z) * hh;
            }
            h2s[wid * 64 + l]      = h2a;
            h2s[wid * 64 + 32 + l] = h2b;
        }
        __syncthreads();              // BAR3: h2(t) published
    }
}

__global__ void __launch_bounds__(256, 2) rnn_kernel(
    const int*   __restrict__ tokens,
    const float* __restrict__ kh1, const float* __restrict__ b1,
    const float* __restrict__ kx2, const float* __restrict__ kh2,
    const float* __restrict__ b2,
    const float* __restrict__ wg,  const float* __restrict__ bg,
    const float* __restrict__ wd,  const float* __restrict__ bd,
    float* __restrict__ out)
{
    extern __shared__ float smemf[];
    u64*   pX   = (u64*)smemf;                    // [4][8][6][32]
    u64*   pRzr = pX + 6144;                      // [4][8][32]
    float* pRh  = (float*)(pRzr + 1024);          // f32[4][8][32]
    float* h1s  = pRh + 1024;                     // f32[4][32]
    float* h2s  = h1s + 128;                      // f32[4][64]
    u64*   bAzr1 = (u64*)(h2s + 256);             // [32]
    float* bG1  = (float*)(bAzr1 + 32);           // [32]
    u64*   bZ2  = (u64*)(bG1 + 32);               // [32]
    u64*   bR2  = bZ2 + 32;
    u64*   bXH2 = bR2 + 32;
    u64*   bHH2 = bXH2 + 32;

    const int tid = threadIdx.x;

    // zero-init state + rec1 partial buffers (h(-1)=0 -> partials = 0)
    for (int i = tid; i < 1024; i += 256) pRzr[i] = 0ull;
    for (int i = tid; i < 1024; i += 256) pRh[i] = 0.0f;
    if (tid < 128) h1s[tid] = 0.0f;
    if (tid < 256) h2s[tid] = 0.0f;
    if (tid < 32) {
        const int v = tid;
        bAzr1[v] = pack2(__ldg(b1 + 96 + v), __ldg(b1 + 128 + v));
        bG1[v]   = __ldg(b1 + 160 + v);
        bZ2[v]   = pack2(__ldg(b2 + v)      + __ldg(b2 + 192 + v),
                         __ldg(b2 + 32 + v) + __ldg(b2 + 224 + v));
        bR2[v]   = pack2(__ldg(b2 + 64 + v) + __ldg(b2 + 256 + v),
                         __ldg(b2 + 96 + v) + __ldg(b2 + 288 + v));
        bXH2[v]  = pack2(__ldg(b2 + 128 + v), __ldg(b2 + 160 + v));
        bHH2[v]  = pack2(__ldg(b2 + 320 + v), __ldg(b2 + 352 + v));
    }
    __syncthreads();

    const int wid = tid >> 5;      // 0..7
    const int l   = tid & 31;

    // block -> elem range: blocks [0,136) own 4 elems, [136,296) own 3 elems
    const int bid = blockIdx.x;
    const bool big = (bid < 136);
    const int ne   = big ? 4 : 3;
    const int base = big ? bid * 4 : 544 + (bid - 136) * 3;
    const bool owns = (wid < ne);
    const int eg = base + (owns ? wid : ne - 1);   // clamped for safety

    // kh2 rows [8w,8w+8): even/odd-j pairs per column (A=col l, B=col l+32)
    u64 wzA[4], wzB[4], wrA[4], wrB[4], whA[4], whB[4];
    {
        const float* wbase = kh2 + (size_t)(wid * 8) * 192;
        #pragma unroll
        for (int p = 0; p < 4; p++) {
            const float* r0 = wbase + (2 * p) * 192;
            const float* r1 = r0 + 192;
            wzA[p] = pack2(__ldg(r0 + l),        __ldg(r1 + l));
            wzB[p] = pack2(__ldg(r0 + 32 + l),   __ldg(r1 + 32 + l));
            wrA[p] = pack2(__ldg(r0 + 64 + l),   __ldg(r1 + 64 + l));
            wrB[p] = pack2(__ldg(r0 + 96 + l),   __ldg(r1 + 96 + l));
            whA[p] = pack2(__ldg(r0 + 128 + l),  __ldg(r1 + 128 + l));
            whB[p] = pack2(__ldg(r0 + 160 + l),  __ldg(r1 + 160 + l));
        }
    }
    // kx2 rows [4w,4w+4): even/odd-j pairs
    u64 xzA[2], xzB[2], xrA[2], xrB[2], xhA[2], xhB[2];
    {
        const float* wbase = kx2 + (size_t)(wid * 4) * 192;
        #pragma unroll
        for (int p = 0; p < 2; p++) {
            const float* r0 = wbase + (2 * p) * 192;
            const float* r1 = r0 + 192;
            xzA[p] = pack2(__ldg(r0 + l),        __ldg(r1 + l));
            xzB[p] = pack2(__ldg(r0 + 32 + l),   __ldg(r1 + 32 + l));
            xrA[p] = pack2(__ldg(r0 + 64 + l),   __ldg(r1 + 64 + l));
            xrB[p] = pack2(__ldg(r0 + 96 + l),   __ldg(r1 + 96 + l));
            xhA[p] = pack2(__ldg(r0 + 128 + l),  __ldg(r1 + 128 + l));
            xhB[p] = pack2(__ldg(r0 + 160 + l),  __ldg(r1 + 160 + l));
        }
    }
    // kh1 rows [4w,4w+4): even/odd-j pairs (cols z=l, r=32+l, h=64+l)
    u64 k1z[2], k1r[2], k1h[2];
    {
        const float* wbase = kh1 + (size_t)(wid * 4) * 96;
        #pragma unroll
        for (int p = 0; p < 2; p++) {
            const float* r0 = wbase + (2 * p) * 96;
            const float* r1 = r0 + 96;
            k1z[p] = pack2(__ldg(r0 + l),       __ldg(r1 + l));
            k1r[p] = pack2(__ldg(r0 + 32 + l),  __ldg(r1 + 32 + l));
            k1h[p] = pack2(__ldg(r0 + 64 + l),  __ldg(r1 + 64 + l));
        }
    }

    const int* tok = tokens + (size_t)eg * NT;
    float h1o = 0.0f, h2a = 0.0f, h2b = 0.0f;

    if (big) rnn_scan<4>(tok, owns, wid, l, pX, pRzr, pRh, h1s, h2s,
                         bAzr1, bG1, bZ2, bR2, bXH2, bHH2,
                         wzA, wzB, wrA, wrB, whA, whB,
                         xzA, xzB, xrA, xrB, xhA, xhB,
                         k1z, k1r, k1h, h1o, h2a, h2b);
    else     rnn_scan<3>(tok, owns, wid, l, pX, pRzr, pRh, h1s, h2s,
                         bAzr1, bG1, bZ2, bR2, bXH2, bHH2,
                         wzA, wzB, wrA, wrB, whA, whB,
                         xzA, xzB, xrA, xrB, xhA, xhB,
                         k1z, k1r, k1h, h1o, h2a, h2b);

    // ---------------- head: a = h2@wg + bg ; GLU ; sigmoid(x@wd + bd) -------
    if (owns) {
        const float* h2e = h2s + wid * 64;
        float acc[8];
        #pragma unroll
        for (int k = 0; k < 8; k++) acc[k] = __ldg(bg + l + 32 * k);
        for (int j = 0; j < NU2; j++) {
            const float hv = h2e[j];
            const float* wrp = wg + j * 256 + l;
            #pragma unroll
            for (int k = 0; k < 8; k++) acc[k] = fmaf(hv, __ldg(wrp + 32 * k), acc[k]);
        }
        float s = 0.0f;
        #pragma unroll
        for (int k = 0; k < 4; k++) {
            const float g = acc[k] * sigf(acc[k + 4]);
            s = fmaf(g, __ldg(wd + l + 32 * k), s);
        }
        #pragma unroll
        for (int off = 16; off >= 1; off >>= 1) s += __shfl_xor_sync(0xffffffffu, s, off);
        if (l == 0) out[eg] = sigf(s + __ldg(bd));
    }
}

// ---------------------------------------------------------------------------
extern "C" void kernel_launch(void* const* d_in, const int* in_sizes, int n_in,
                              void* d_out, int out_size) {
    const int*   tokens = (const int*)d_in[0];
    const float* emb = (const float*)d_in[1];
    const float* kx1 = (const float*)d_in[2];
    const float* kh1 = (const float*)d_in[3];
    const float* b1  = (const float*)d_in[4];
    const float* kx2 = (const float*)d_in[5];
    const float* kh2 = (const float*)d_in[6];
    const float* b2  = (const float*)d_in[7];
    const float* wg  = (const float*)d_in[8];
    const float* bg  = (const float*)d_in[9];
    const float* wd  = (const float*)d_in[10];
    const float* bd  = (const float*)d_in[11];
    float* out = (float*)d_out;

    const size_t smem_bytes = SMEM_FLOATS * sizeof(float);
    cudaFuncSetAttribute(rnn_kernel, cudaFuncAttributeMaxDynamicSharedMemorySize, (int)smem_bytes);

    embproj_kernel<<<(VOCAB + 15) / 16, 96>>>(emb, kx1, b1);
    rnn_kernel<<<296, 256, smem_bytes>>>(tokens, kh1, b1, kx2, kh2, b2, wg, bg, wd, bd, out);
}

// round 16
// speedup vs baseline: 1.0230x; 1.0230x over previous
#include <cuda_runtime.h>

constexpr int VOCAB = 50257;
constexpr int DIM   = 50;
constexpr int NU2   = 64;
constexpr int NB    = 1024;
constexpr int NT    = 1024;

using u64 = unsigned long long;

// Precomputed embedding projection: embproj[v][k] = emb[v]@kx1[:,k] + b1[0][k]
// 50257*96 floats = 19.3 MB -> L2 resident during the recurrent kernel.
__device__ float g_embproj[(size_t)VOCAB * 96];

__device__ __forceinline__ u64 pack2(float lo, float hi) {
    u64 r; asm("mov.b64 %0, {%1, %2};" : "=l"(r) : "f"(lo), "f"(hi)); return r;
}
__device__ __forceinline__ void unpack2(u64 p, float& lo, float& hi) {
    asm("mov.b64 {%0, %1}, %2;" : "=f"(lo), "=f"(hi) : "l"(p));
}
__device__ __forceinline__ u64 fma2(u64 a, u64 b, u64 c) {
    u64 d; asm("fma.rn.f32x2 %0, %1, %2, %3;" : "=l"(d) : "l"(a), "l"(b), "l"(c)); return d;
}
__device__ __forceinline__ u64 add2(u64 a, u64 b) {
    u64 d; asm("add.rn.f32x2 %0, %1, %2;" : "=l"(d) : "l"(a), "l"(b)); return d;
}
__device__ __forceinline__ float hsum2(u64 p) {
    float lo, hi; unpack2(p, lo, hi); return lo + hi;
}
// Fast activations via single-MUFU tanh (sm_75+). abs err ~1e-5, fine vs 1e-3.
__device__ __forceinline__ float tanh_mufu(float x) {
    float t; asm("tanh.approx.f32 %0, %1;" : "=f"(t) : "f"(x)); return t;
}
__device__ __forceinline__ float sigf(float x) {
    return fmaf(tanh_mufu(0.5f * x), 0.5f, 0.5f);
}

// ---------------------------------------------------------------------------
// Kernel A: embproj = emb @ kx1 + b1[0]
// ---------------------------------------------------------------------------
__global__ void __launch_bounds__(96) embproj_kernel(const float* __restrict__ emb,
                                                     const float* __restrict__ kx1,
                                                     const float* __restrict__ b1) {
    __shared__ float kx1s[DIM * 96];
    __shared__ float xrow[DIM];
    const int tid = threadIdx.x;
    for (int i = tid; i < DIM * 96; i += 96) kx1s[i] = kx1[i];
    const float bc = b1[tid];
    __syncthreads();
    const int row0 = blockIdx.x * 16;
    for (int k = 0; k < 16; k++) {
        const int row = row0 + k;
        if (row >= VOCAB) break;
        if (tid < DIM) xrow[tid] = emb[(size_t)row * DIM + tid];
        __syncthreads();
        float acc = bc;
        #pragma unroll
        for (int d = 0; d < DIM; d++) acc = fmaf(xrow[d], kx1s[d * 96 + tid], acc);
        g_embproj[(size_t)row * 96 + tid] = acc;
        __syncthreads();
    }
}

// ---------------------------------------------------------------------------
// Kernel B: fused GRU1 -> GRU2 -> GLU -> dense.
// 296 blocks x 256 threads (8 warps), 2 CTAs/SM -> 16 warps/SM = 4/SMSP.
// ROW x COLUMN 2D weight split: warp = (ws = wid&3 row-group, cs = wid>>2
// column half). Each warp holds kh2 rows [16ws,16ws+16) x cols
// [32cs,32cs+32) and kx2 rows [8ws,8ws+8) x same cols. Fan-in per partial
// stays 4 (same smem partial bytes as R13) while warps/SM doubles -- the
// fix for R14's fan-in-8 crossbar blowup. Partials are scalar f32 per lane.
// cs0 warps: GRU1 combine + head. cs1 warps: rec1 partials (hold kh1).
// Same 3-phase step:
//   A: GRU1 combine -> h1(t) [cs0]; rec2 partials -> pX 3..5 [all];  BAR1
//   B: xproj2 partials -> pX 0..2 [all]; rec1(t+1) -> pR [cs1];      BAR2
//   C: combine -> GRU2 gates -> h2(t) col half [owners both cs];     BAR3
//
// smem layout (f32 offsets), TOTAL = 9472 floats = 37.9 KB/CTA:
//   [0,6144)      pX    f32[4 elems][4 ws][6 slots][64 cols]
//   [6144,8192)   pRzr  u64[4][4][32]  (512 u64; region reserved 2048 f32)
//   [8192,8704)   pRh   f32[4][4][32]
//   [8704,8832)   h1s   f32[4][32]
//   [8832,9088)   h2s   f32[4][64]
//   [9088,9152)   bAzr1 u64[32]
//   [9152,9184)   bG1   f32[32]
//   [9184,9440)   bZ2/bR2/bXH2/bHH2 f32[64] each
// ---------------------------------------------------------------------------
constexpr int SMEM_FLOATS = 9472;   // layout ends at 9440; padded

template<int NE>
__device__ __forceinline__ void rnn_scan(
    const int* __restrict__ tok, bool owner, bool cs0, bool cs1,
    int ws, int l, int c,
    float* pX, u64* pRzr, float* pRh, float* h1s, float* h2s,
    const u64* bAzr1, const float* bG1, const float* bZ2, const float* bR2,
    const float* bXH2, const float* bHH2,
    const u64* wz, const u64* wr, const u64* wh,
    const u64* xz2, const u64* xr2, const u64* xh2,
    const u64* k1z, const u64* k1r, const u64* k1h,
    float& h1o, float& h2x)
{
    // --- prologue: embproj gather for t=0 (cs0 owners only) ---
    int tk = 0;
    float exz = 0.0f, exr = 0.0f, exh = 0.0f;
    const bool gru1w = owner && cs0;
    if (gru1w) {
        tk = tok[l];
        const int ti = __shfl_sync(0xffffffffu, tk, 0);
        const float* ep = g_embproj + (size_t)ti * 96;
        exz = __ldg(ep + l); exr = __ldg(ep + 32 + l); exh = __ldg(ep + 64 + l);
    }

    for (int t = 0; t < NT; t++) {
        // ===== Phase A =====================================================
        // GRU1 combine first on cs0 owners (hides under rec2 fma2 stream).
        if (gru1w) {
            u64 zr = bAzr1[l]; float hm = bG1[l];
            #pragma unroll
            for (int w = 0; w < 4; w++) {
                zr = add2(zr, pRzr[(ws * 4 + w) * 32 + l]);
                hm += pRh[(ws * 4 + w) * 32 + l];
            }
            float az, ar; unpack2(zr, az, ar);
            const float z = sigf(exz + az), r = sigf(exr + ar);
            const float hh = tanh_mufu(exh + r * hm);
            h1o = z * h1o + (1.0f - z) * hh;
            h1s[ws * 32 + l] = h1o;
        }

        // rec2 partials: kh2 rows [16ws,16ws+16) x col c, all NE elems.
        #pragma unroll
        for (int e = 0; e < NE; e++) {
            const ulonglong2* hp = (const ulonglong2*)(h2s + e * 64 + ws * 16);
            const ulonglong2 q0 = hp[0], q1 = hp[1], q2 = hp[2], q3 = hp[3];
            u64 az = 0ull, ar = 0ull, ah = 0ull;
            az = fma2(wz[0], q0.x, az); ar = fma2(wr[0], q0.x, ar); ah = fma2(wh[0], q0.x, ah);
            az = fma2(wz[1], q0.y, az); ar = fma2(wr[1], q0.y, ar); ah = fma2(wh[1], q0.y, ah);
            az = fma2(wz[2], q1.x, az); ar = fma2(wr[2], q1.x, ar); ah = fma2(wh[2], q1.x, ah);
            az = fma2(wz[3], q1.y, az); ar = fma2(wr[3], q1.y, ar); ah = fma2(wh[3], q1.y, ah);
            az = fma2(wz[4], q2.x, az); ar = fma2(wr[4], q2.x, ar); ah = fma2(wh[4], q2.x, ah);
            az = fma2(wz[5], q2.y, az); ar = fma2(wr[5], q2.y, ar); ah = fma2(wh[5], q2.y, ah);
            az = fma2(wz[6], q3.x, az); ar = fma2(wr[6], q3.x, ar); ah = fma2(wh[6], q3.x, ah);
            az = fma2(wz[7], q3.y, az); ar = fma2(wr[7], q3.y, ar); ah = fma2(wh[7], q3.y, ah);
            float* pb = pX + (size_t)((e * 4 + ws) * 6) * 64 + c;
            pb[3 * 64] = hsum2(az);
            pb[4 * 64] = hsum2(ar);
            pb[5 * 64] = hsum2(ah);
        }

        // prefetch embproj for t+1
        if (gru1w && t + 1 < NT) {
            if (((t + 1) & 31) == 0) tk = tok[t + 1 + l];
            const int ti = __shfl_sync(0xffffffffu, tk, (t + 1) & 31);
            const float* ep = g_embproj + (size_t)ti * 96;
            exz = __ldg(ep + l); exr = __ldg(ep + 32 + l); exh = __ldg(ep + 64 + l);
        }
        __syncthreads();              // BAR1: h1(t), rec2 partials published

        // ===== Phase B: xproj2 [all] + rec1(t+1) [cs1] =====================
        #pragma unroll
        for (int e = 0; e < NE; e++) {
            const ulonglong2* hq = (const ulonglong2*)(h1s + e * 32 + ws * 8);
            const ulonglong2 q0 = hq[0], q1 = hq[1];
            u64 sz = 0ull, sr = 0ull, sh = 0ull;
            sz = fma2(xz2[0], q0.x, sz); sr = fma2(xr2[0], q0.x, sr); sh = fma2(xh2[0], q0.x, sh);
            sz = fma2(xz2[1], q0.y, sz); sr = fma2(xr2[1], q0.y, sr); sh = fma2(xh2[1], q0.y, sh);
            sz = fma2(xz2[2], q1.x, sz); sr = fma2(xr2[2], q1.x, sr); sh = fma2(xh2[2], q1.x, sh);
            sz = fma2(xz2[3], q1.y, sz); sr = fma2(xr2[3], q1.y, sr); sh = fma2(xh2[3], q1.y, sh);
            float* pb = pX + (size_t)((e * 4 + ws) * 6) * 64 + c;
            pb[0]      = hsum2(sz);
            pb[1 * 64] = hsum2(sr);
            pb[2 * 64] = hsum2(sh);
            if (cs1) {
                u64 rz = 0ull, rr = 0ull, rh = 0ull;
                rz = fma2(k1z[0], q0.x, rz); rr = fma2(k1r[0], q0.x, rr); rh = fma2(k1h[0], q0.x, rh);
                rz = fma2(k1z[1], q0.y, rz); rr = fma2(k1r[1], q0.y, rr); rh = fma2(k1h[1], q0.y, rh);
                rz = fma2(k1z[2], q1.x, rz); rr = fma2(k1r[2], q1.x, rr); rh = fma2(k1h[2], q1.x, rh);
                rz = fma2(k1z[3], q1.y, rz); rr = fma2(k1r[3], q1.y, rr); rh = fma2(k1h[3], q1.y, rh);
                pRzr[(e * 4 + ws) * 32 + l] = pack2(hsum2(rz), hsum2(rr));
                pRh [(e * 4 + ws) * 32 + l] = hsum2(rh);
            }
        }
        __syncthreads();              // BAR2: partials published

        // ===== Phase C: combine col-half c of own elem -> h2(t) ============
        if (owner) {
            float zp = bZ2[c], rp = bR2[c], xp = bXH2[c], hm = bHH2[c];
            #pragma unroll
            for (int w = 0; w < 4; w++) {
                const float* pb = pX + (size_t)((ws * 4 + w) * 6) * 64 + c;
                zp += pb[0]      + pb[3 * 64];
                rp += pb[1 * 64] + pb[4 * 64];
                xp += pb[2 * 64];
                hm += pb[5 * 64];
            }
            const float z = sigf(zp), r = sigf(rp);
            const float hh = tanh_mufu(xp + r * hm);
            h2x = z * h2x + (1.0f - z) * hh;
            h2s[ws * 64 + c] = h2x;
        }
        __syncthreads();              // BAR3: h2(t) published
    }
}

__global__ void __launch_bounds__(256, 2) rnn_kernel(
    const int*   __restrict__ tokens,
    const float* __restrict__ kh1, const float* __restrict__ b1,
    const float* __restrict__ kx2, const float* __restrict__ kh2,
    const float* __restrict__ b2,
    const float* __restrict__ wg,  const float* __restrict__ bg,
    const float* __restrict__ wd,  const float* __restrict__ bd,
    float* __restrict__ out)
{
    extern __shared__ float smemf[];
    float* pX    = smemf;                         // f32[4][4][6][64]  = 6144
    u64*   pRzr  = (u64*)(smemf + 6144);          // u64[4][4][32]; region 2048 f32
    float* pRh   = smemf + 6144 + 2048;           // f32[4][4][32]     =  512
    float* h1s   = pRh + 512;                     // f32[4][32]
    float* h2s   = h1s + 128;                     // f32[4][64]
    u64*   bAzr1 = (u64*)(h2s + 256);             // u64[32] (64 f32)
    float* bG1   = (float*)(bAzr1 + 32);          // f32[32]
    float* bZ2   = bG1 + 32;                      // f32[64]
    float* bR2   = bZ2 + 64;
    float* bXH2  = bR2 + 64;
    float* bHH2  = bXH2 + 64;                     // ends at f32 offset 9440

    const int tid = threadIdx.x;

    // zero-init rec1 partial region [6144,8192)+pRh, state
    for (int i = tid; i < 1024; i += 256) pRzr[i] = 0ull;     // covers [6144,8192)
    for (int i = tid; i < 512;  i += 256) pRh[i] = 0.0f;
    if (tid < 128) h1s[tid] = 0.0f;
    if (tid < 256) h2s[tid] = 0.0f;
    if (tid < 32) {
        bAzr1[tid] = pack2(__ldg(b1 + 96 + tid), __ldg(b1 + 128 + tid));
        bG1[tid]   = __ldg(b1 + 160 + tid);
    }
    if (tid < 64) {
        bZ2[tid]  = __ldg(b2 + tid)       + __ldg(b2 + 192 + tid);
        bR2[tid]  = __ldg(b2 + 64 + tid)  + __ldg(b2 + 256 + tid);
        bXH2[tid] = __ldg(b2 + 128 + tid);
        bHH2[tid] = __ldg(b2 + 320 + tid);
    }
    __syncthreads();

    const int wid = tid >> 5;        // 0..7
    const int l   = tid & 31;
    const int ws  = wid & 3;         // row-group
    const int cs  = wid >> 2;        // column half (0 or 1)
    const int c   = cs * 32 + l;     // this lane's GRU2 column

    // block -> elem range: blocks [0,136) own 4 elems, [136,296) own 3 elems
    const int bid = blockIdx.x;
    const bool big = (bid < 136);
    const int ne   = big ? 4 : 3;
    const int base = big ? bid * 4 : 544 + (bid - 136) * 3;
    const bool owner = (ws < ne);
    const int eg = base + (owner ? ws : ne - 1);   // clamped

    // kh2 rows [16ws,16ws+16) x col c: even/odd row pairs
    u64 wz[8], wr[8], wh[8];
    {
        const float* wbase = kh2 + (size_t)(ws * 16) * 192;
        #pragma unroll
        for (int p = 0; p < 8; p++) {
            const float* r0 = wbase + (2 * p) * 192;
            const float* r1 = r0 + 192;
            wz[p] = pack2(__ldg(r0 + c),       __ldg(r1 + c));
            wr[p] = pack2(__ldg(r0 + 64 + c),  __ldg(r1 + 64 + c));
            wh[p] = pack2(__ldg(r0 + 128 + c), __ldg(r1 + 128 + c));
        }
    }
    // kx2 rows [8ws,8ws+8) x col c
    u64 xz2[4], xr2[4], xh2[4];
    {
        const float* wbase = kx2 + (size_t)(ws * 8) * 192;
        #pragma unroll
        for (int p = 0; p < 4; p++) {
            const float* r0 = wbase + (2 * p) * 192;
            const float* r1 = r0 + 192;
            xz2[p] = pack2(__ldg(r0 + c),       __ldg(r1 + c));
            xr2[p] = pack2(__ldg(r0 + 64 + c),  __ldg(r1 + 64 + c));
            xh2[p] = pack2(__ldg(r0 + 128 + c), __ldg(r1 + 128 + c));
        }
    }
    // kh1 rows [8ws,8ws+8) (cs1 warps only; zero regs otherwise)
    u64 k1z[4] = {0,0,0,0}, k1r[4] = {0,0,0,0}, k1h[4] = {0,0,0,0};
    if (cs == 1) {
        const float* wbase = kh1 + (size_t)(ws * 8) * 96;
        #pragma unroll
        for (int p = 0; p < 4; p++) {
            const float* r0 = wbase + (2 * p) * 96;
            const float* r1 = r0 + 96;
            k1z[p] = pack2(__ldg(r0 + l),       __ldg(r1 + l));
            k1r[p] = pack2(__ldg(r0 + 32 + l),  __ldg(r1 + 32 + l));
            k1h[p] = pack2(__ldg(r0 + 64 + l),  __ldg(r1 + 64 + l));
        }
    }

    const int* tok = tokens + (size_t)eg * NT;
    float h1o = 0.0f, h2x = 0.0f;

    if (big) rnn_scan<4>(tok, owner, cs == 0, cs == 1, ws, l, c,
                         pX, pRzr, pRh, h1s, h2s,
                         bAzr1, bG1, bZ2, bR2, bXH2, bHH2,
                         wz, wr, wh, xz2, xr2, xh2, k1z, k1r, k1h, h1o, h2x);
    else     rnn_scan<3>(tok, owner, cs == 0, cs == 1, ws, l, c,
                         pX, pRzr, pRh, h1s, h2s,
                         bAzr1, bG1, bZ2, bR2, bXH2, bHH2,
                         wz, wr, wh, xz2, xr2, xh2, k1z, k1r, k1h, h1o, h2x);

    // ---------------- head: a = h2@wg + bg ; GLU ; sigmoid(x@wd + bd) -------
    if (owner && cs == 0) {
        const float* h2e = h2s + ws * 64;
        float acc[8];
        #pragma unroll
        for (int k = 0; k < 8; k++) acc[k] = __ldg(bg + l + 32 * k);
        for (int j = 0; j < NU2; j++) {
            const float hv = h2e[j];
            const float* wrp = wg + j * 256 + l;
            #pragma unroll
            for (int k = 0; k < 8; k++) acc[k] = fmaf(hv, __ldg(wrp + 32 * k), acc[k]);
        }
        float s = 0.0f;
        #pragma unroll
        for (int k = 0; k < 4; k++) {
            const float g = acc[k] * sigf(acc[k + 4]);
            s = fmaf(g, __ldg(wd + l + 32 * k), s);
        }
        #pragma unroll
        for (int off = 16; off >= 1; off >>= 1) s += __shfl_xor_sync(0xffffffffu, s, off);
        if (l == 0) out[eg] = sigf(s + __ldg(bd));
    }
}

// ---------------------------------------------------------------------------
extern "C" void kernel_launch(void* const* d_in, const int* in_sizes, int n_in,
                              void* d_out, int out_size) {
    const int*   tokens = (const int*)d_in[0];
    const float* emb = (const float*)d_in[1];
    const float* kx1 = (const float*)d_in[2];
    const float* kh1 = (const float*)d_in[3];
    const float* b1  = (const float*)d_in[4];
    const float* kx2 = (const float*)d_in[5];
    const float* kh2 = (const float*)d_in[6];
    const float* b2  = (const float*)d_in[7];
    const float* wg  = (const float*)d_in[8];
    const float* bg  = (const float*)d_in[9];
    const float* wd  = (const float*)d_in[10];
    const float* bd  = (const float*)d_in[11];
    float* out = (float*)d_out;

    const size_t smem_bytes = SMEM_FLOATS * sizeof(float);
    cudaFuncSetAttribute(rnn_kernel, cudaFuncAttributeMaxDynamicSharedMemorySize, (int)smem_bytes);

    embproj_kernel<<<(VOCAB + 15) / 16, 96>>>(emb, kx1, b1);
    rnn_kernel<<<296, 256, smem_bytes>>>(tokens, kh1, b1, kx2, kh2, b2, wg, bg, wd, bd, out);
}